// round 1
// baseline (speedup 1.0000x reference)
#include <cuda_runtime.h>

#define NN   8192
#define KP1  4096
#define KP2  2048
#define FF   32
#define FIN  16
#define CAPN (1 << 22)   // 4M nnz capacity (expected ~1.33M)

// ---------------- device scratch (static globals; no allocations) -------------
__device__ int    g_cursor;
__device__ int    g_rowstart[NN];
__device__ int    g_rowcnt[NN];
__device__ int    g_cols[CAPN];
__device__ float  g_dinv[NN];
__device__ float  g_dinvs[KP1];
__device__ float  g_G1[NN * FF];
__device__ float  g_X1[NN * FF];
__device__ float  g_G2[KP1 * FF];
__device__ float  g_X2[KP1 * FF];
__device__ float  g_G3[KP1 * FF];
__device__ float  g_X3[KP1 * FF];
__device__ float2 g_G4[NN];
__device__ float  g_score1[NN];
__device__ float  g_score2[KP1];
__device__ int    g_rank1[NN];
__device__ int    g_rank2[KP1];
__device__ int    g_idx1[KP1];
__device__ int    g_idx2[KP2];

// ---------------- kernels -----------------------------------------------------

__global__ void k_reset() { g_cursor = 0; }

// One streaming pass over dense A: build CSR (binary values -> cols only) and
// degree-based normalizer dinv[i] = rsqrt(rowsum + 1 + eps).
__global__ void k_build_csr(const float* __restrict__ A) {
    int row = blockIdx.x;
    int t   = threadIdx.x;
    const float4* ar = reinterpret_cast<const float4*>(A + (size_t)row * NN);

    float4 v[8];
    int c = 0;
#pragma unroll
    for (int k = 0; k < 8; k++) {
        v[k] = __ldcs(ar + k * 256 + t);          // coalesced, evict-first
        c += (v[k].x != 0.f) + (v[k].y != 0.f) + (v[k].z != 0.f) + (v[k].w != 0.f);
    }

    __shared__ int sc[256];
    sc[t] = c;
    __syncthreads();
#pragma unroll
    for (int o = 1; o < 256; o <<= 1) {
        int add = (t >= o) ? sc[t - o] : 0;
        __syncthreads();
        sc[t] += add;
        __syncthreads();
    }
    int incl  = sc[t];
    int total = sc[255];

    __shared__ int sbase;
    if (t == 0) {
        int base = atomicAdd(&g_cursor, total);
        if (base + total > CAPN) base = 0;        // safety; never expected
        sbase = base;
        g_rowstart[row] = base;
        g_rowcnt[row]   = total;
        g_dinv[row]     = rsqrtf((float)total + 1.0f + 1e-10f);
    }
    __syncthreads();

    int pos = sbase + incl - c;
#pragma unroll
    for (int k = 0; k < 8; k++) {
        int col0 = (k * 256 + t) * 4;
        if (v[k].x != 0.f) g_cols[pos++] = col0 + 0;
        if (v[k].y != 0.f) g_cols[pos++] = col0 + 1;
        if (v[k].z != 0.f) g_cols[pos++] = col0 + 2;
        if (v[k].w != 0.f) g_cols[pos++] = col0 + 3;
    }
}

// G1[i,:] = dinv[i] * (x[i,:] @ W1)     (warp per row, lane per out-feature)
__global__ void k_g1(const float* __restrict__ x, const float* __restrict__ W1) {
    __shared__ float w[FIN * FF];
    for (int i = threadIdx.x; i < FIN * FF; i += blockDim.x) w[i] = W1[i];
    __syncthreads();
    int warp = (blockIdx.x * blockDim.x + threadIdx.x) >> 5;
    int lane = threadIdx.x & 31;
    if (warp >= NN) return;
    float xv = (lane < FIN) ? x[warp * FIN + lane] : 0.f;
    float acc = 0.f;
#pragma unroll
    for (int f = 0; f < FIN; f++) {
        float xf = __shfl_sync(0xffffffffu, xv, f);
        acc += xf * w[f * FF + lane];
    }
    g_G1[warp * FF + lane] = g_dinv[warp] * acc;
}

// X1[i,:] = relu(dinv[i] * (sum_{j in adj(i)} G1[j,:] + G1[i,:])); score1 = X1 . s1
__global__ void k_spmm_main(const float* __restrict__ s1) {
    __shared__ float sv[FF];
    if (threadIdx.x < FF) sv[threadIdx.x] = s1[threadIdx.x];
    __syncthreads();
    int warp = (blockIdx.x * blockDim.x + threadIdx.x) >> 5;
    int lane = threadIdx.x & 31;
    if (warp >= NN) return;
    int base = g_rowstart[warp], cnt = g_rowcnt[warp];
    float acc = g_G1[warp * FF + lane];          // identity (+I) term
    int k = 0, end4 = cnt & ~3;
    for (; k < end4; k += 4) {
        int c0 = g_cols[base + k + 0];
        int c1 = g_cols[base + k + 1];
        int c2 = g_cols[base + k + 2];
        int c3 = g_cols[base + k + 3];
        float a0 = g_G1[c0 * FF + lane];
        float a1 = g_G1[c1 * FF + lane];
        float a2 = g_G1[c2 * FF + lane];
        float a3 = g_G1[c3 * FF + lane];
        acc += a0; acc += a1; acc += a2; acc += a3;
    }
    for (; k < cnt; k++) acc += g_G1[g_cols[base + k] * FF + lane];
    float y = fmaxf(g_dinv[warp] * acc, 0.f);
    g_X1[warp * FF + lane] = y;
    float s = y * sv[lane];
#pragma unroll
    for (int o = 16; o > 0; o >>= 1) s += __shfl_down_sync(0xffffffffu, s, o);
    if (lane == 0) g_score1[warp] = s;
}

// Exact top-K set via single-block radix select + deterministic ordered
// compaction. which==0: score1/N/K1 -> idx1, rank1. which==1: score2/K1/K2.
__global__ void k_topk(int which) {
    const float* scores = which ? g_score2 : g_score1;
    int  n        = which ? KP1 : NN;
    int  K        = which ? KP2 : KP1;
    int* idx_out  = which ? g_idx2 : g_idx1;
    int* rank_out = which ? g_rank2 : g_rank1;

    __shared__ unsigned su[NN];
    __shared__ int hist[256];
    __shared__ int wsum[32];
    __shared__ int sh_prefix, sh_need, sh_selbase, sh_eqbase;

    int t = threadIdx.x, nt = blockDim.x;
    for (int i = t; i < n; i += nt) {
        unsigned b = __float_as_uint(scores[i]);
        su[i] = (b & 0x80000000u) ? ~b : (b | 0x80000000u);   // order-preserving
    }
    if (t == 0) { sh_prefix = 0; sh_need = K; sh_selbase = 0; sh_eqbase = 0; }
    __syncthreads();

    for (int shift = 24; shift >= 0; shift -= 8) {
        for (int i = t; i < 256; i += nt) hist[i] = 0;
        __syncthreads();
        unsigned pfx = (unsigned)sh_prefix;
        int hs = shift + 8;
        for (int i = t; i < n; i += nt) {
            unsigned u  = su[i];
            unsigned ha = (hs >= 32) ? 0u : (u >> hs);
            unsigned hb = (hs >= 32) ? 0u : (pfx >> hs);
            if (ha == hb) atomicAdd(&hist[(u >> shift) & 255], 1);
        }
        __syncthreads();
        if (t == 0) {
            int need = sh_need;
            int b = 255;
            while (b > 0 && hist[b] < need) { need -= hist[b]; b--; }
            sh_prefix = (int)(pfx | ((unsigned)b << shift));
            sh_need = need;
        }
        __syncthreads();
    }
    unsigned T = (unsigned)sh_prefix;   // exact K-th largest value
    int need_eq = sh_need;              // how many ==T to take (lowest indices)
    int lane = t & 31, wid = t >> 5;

    int nchunk = (n + nt - 1) / nt;
    for (int ch = 0; ch < nchunk; ch++) {
        int i = ch * nt + t;
        int fgt = 0, feq = 0;
        if (i < n) { unsigned u = su[i]; fgt = (u > T); feq = (u == T); }

        // block scan of feq
        int x = feq;
#pragma unroll
        for (int o = 1; o < 32; o <<= 1) { int y = __shfl_up_sync(0xffffffffu, x, o); if (lane >= o) x += y; }
        if (lane == 31) wsum[wid] = x;
        __syncthreads();
        if (wid == 0) {
            int w = wsum[lane];
#pragma unroll
            for (int o = 1; o < 32; o <<= 1) { int y = __shfl_up_sync(0xffffffffu, w, o); if (lane >= o) w += y; }
            wsum[lane] = w;
        }
        __syncthreads();
        int eq_incl = x + (wid > 0 ? wsum[wid - 1] : 0);
        __syncthreads();

        int eq_rank = sh_eqbase + eq_incl - feq;
        int sel = (fgt || (feq && eq_rank < need_eq)) ? 1 : 0;

        // block scan of sel
        int xs = sel;
#pragma unroll
        for (int o = 1; o < 32; o <<= 1) { int y = __shfl_up_sync(0xffffffffu, xs, o); if (lane >= o) xs += y; }
        if (lane == 31) wsum[wid] = xs;
        __syncthreads();
        if (wid == 0) {
            int w = wsum[lane];
#pragma unroll
            for (int o = 1; o < 32; o <<= 1) { int y = __shfl_up_sync(0xffffffffu, w, o); if (lane >= o) w += y; }
            wsum[lane] = w;
        }
        __syncthreads();
        int s_incl = xs + (wid > 0 ? wsum[wid - 1] : 0);
        int pos = sh_selbase + s_incl - sel;

        if (i < n) {
            if (sel) { rank_out[i] = pos; idx_out[pos] = i; }
            else       rank_out[i] = -1;
        }
        __syncthreads();
        if (t == nt - 1) { sh_eqbase += eq_incl; sh_selbase += s_incl; }
        __syncthreads();
    }
}

// Subgraph degrees: deg_sub[r] = #{c in adj(idx1[r]) : rank1[c]>=0} + 1
__global__ void k_subdeg() {
    int warp = (blockIdx.x * blockDim.x + threadIdx.x) >> 5;
    int lane = threadIdx.x & 31;
    if (warp >= KP1) return;
    int i = g_idx1[warp];
    int base = g_rowstart[i], cnt = g_rowcnt[i];
    int c = 0;
    for (int k = lane; k < cnt; k += 32) c += (g_rank1[g_cols[base + k]] >= 0);
#pragma unroll
    for (int o = 16; o > 0; o >>= 1) c += __shfl_down_sync(0xffffffffu, c, o);
    if (lane == 0) g_dinvs[warp] = rsqrtf((float)c + 1.0f + 1e-10f);
}

// G2[r,:] = dinvs[r] * (X1[idx1[r],:] @ W2)
__global__ void k_g2(const float* __restrict__ W2) {
    __shared__ float w[FF * FF];
    for (int i = threadIdx.x; i < FF * FF; i += blockDim.x) w[i] = W2[i];
    __syncthreads();
    int warp = (blockIdx.x * blockDim.x + threadIdx.x) >> 5;
    int lane = threadIdx.x & 31;
    if (warp >= KP1) return;
    int i = g_idx1[warp];
    float xv = g_X1[i * FF + lane];
    float acc = 0.f;
#pragma unroll
    for (int f = 0; f < FF; f++) {
        float xf = __shfl_sync(0xffffffffu, xv, f);
        acc += xf * w[f * FF + lane];
    }
    g_G2[warp * FF + lane] = g_dinvs[warp] * acc;
}

// G3[r,:] = (rank2[r]>=0) ? dinvs[r] * (X2[r,:] @ W3) : 0   (unpool mask fused)
__global__ void k_g3(const float* __restrict__ W3) {
    __shared__ float w[FF * FF];
    for (int i = threadIdx.x; i < FF * FF; i += blockDim.x) w[i] = W3[i];
    __syncthreads();
    int warp = (blockIdx.x * blockDim.x + threadIdx.x) >> 5;
    int lane = threadIdx.x & 31;
    if (warp >= KP1) return;
    if (g_rank2[warp] < 0) { g_G3[warp * FF + lane] = 0.f; return; }
    float xv = g_X2[warp * FF + lane];
    float acc = 0.f;
#pragma unroll
    for (int f = 0; f < FF; f++) {
        float xf = __shfl_sync(0xffffffffu, xv, f);
        acc += xf * w[f * FF + lane];
    }
    g_G3[warp * FF + lane] = g_dinvs[warp] * acc;
}

// Subgraph SpMM: Xout[r,:] = relu(dinvs[r]*(sum_{c: rank1[c]>=0} Gin[rank1[c],:] + Gin[r,:]))
// phase 0: G2->X2 (+score2 with s2). phase 1: G3->X3 (no score).
__global__ void k_spmm_sub(int phase, const float* __restrict__ svec) {
    __shared__ float sv[FF];
    if (phase == 0 && threadIdx.x < FF) sv[threadIdx.x] = svec[threadIdx.x];
    __syncthreads();
    const float* Gin = phase ? g_G3 : g_G2;
    float*       Xout = phase ? g_X3 : g_X2;
    int warp = (blockIdx.x * blockDim.x + threadIdx.x) >> 5;
    int lane = threadIdx.x & 31;
    if (warp >= KP1) return;
    int i = g_idx1[warp];
    int base = g_rowstart[i], cnt = g_rowcnt[i];
    float acc = Gin[warp * FF + lane];           // identity term
    int k = 0, end4 = cnt & ~3;
    for (; k < end4; k += 4) {
        int r0 = g_rank1[g_cols[base + k + 0]];
        int r1 = g_rank1[g_cols[base + k + 1]];
        int r2 = g_rank1[g_cols[base + k + 2]];
        int r3 = g_rank1[g_cols[base + k + 3]];
        if (r0 >= 0) acc += Gin[r0 * FF + lane];
        if (r1 >= 0) acc += Gin[r1 * FF + lane];
        if (r2 >= 0) acc += Gin[r2 * FF + lane];
        if (r3 >= 0) acc += Gin[r3 * FF + lane];
    }
    for (; k < cnt; k++) {
        int rr = g_rank1[g_cols[base + k]];
        if (rr >= 0) acc += Gin[rr * FF + lane];
    }
    float y = fmaxf(g_dinvs[warp] * acc, 0.f);
    Xout[warp * FF + lane] = y;
    if (phase == 0) {
        float s = y * sv[lane];
#pragma unroll
        for (int o = 16; o > 0; o >>= 1) s += __shfl_down_sync(0xffffffffu, s, o);
        if (lane == 0) g_score2[warp] = s;
    }
}

// G4[i] = dinv[i] * (X4[i,:] @ W4), X4[i] = (rank1[i]>=0) ? X3[rank1[i]] : 0
__global__ void k_g4(const float* __restrict__ W4) {
    __shared__ float w[FF * 2];
    for (int i = threadIdx.x; i < FF * 2; i += blockDim.x) w[i] = W4[i];
    __syncthreads();
    int i = blockIdx.x * blockDim.x + threadIdx.x;
    if (i >= NN) return;
    int rr = g_rank1[i];
    float h0 = 0.f, h1 = 0.f;
    if (rr >= 0) {
        const float* xr = g_X3 + rr * FF;
#pragma unroll
        for (int f = 0; f < FF; f++) {
            float xf = xr[f];
            h0 += xf * w[f * 2 + 0];
            h1 += xf * w[f * 2 + 1];
        }
    }
    float d = g_dinv[i];
    g_G4[i] = make_float2(d * h0, d * h1);
}

// Final SpMM (F=2) + normalization + 2-way softmax
__global__ void k_final(float* __restrict__ out) {
    int warp = (blockIdx.x * blockDim.x + threadIdx.x) >> 5;
    int lane = threadIdx.x & 31;
    if (warp >= NN) return;
    int base = g_rowstart[warp], cnt = g_rowcnt[warp];
    float a0 = 0.f, a1 = 0.f;
    for (int k = lane; k < cnt; k += 32) {
        float2 g = g_G4[g_cols[base + k]];
        a0 += g.x; a1 += g.y;
    }
#pragma unroll
    for (int o = 16; o > 0; o >>= 1) {
        a0 += __shfl_down_sync(0xffffffffu, a0, o);
        a1 += __shfl_down_sync(0xffffffffu, a1, o);
    }
    if (lane == 0) {
        float2 gs = g_G4[warp];
        float d = g_dinv[warp];
        float y0 = d * (a0 + gs.x);
        float y1 = d * (a1 + gs.y);
        float m = fmaxf(y0, y1);
        float e0 = expf(y0 - m);
        float e1 = expf(y1 - m);
        float inv = 1.0f / (e0 + e1);
        out[warp * 2 + 0] = e0 * inv;
        out[warp * 2 + 1] = e1 * inv;
    }
}

// ---------------- launcher ----------------------------------------------------
extern "C" void kernel_launch(void* const* d_in, const int* in_sizes, int n_in,
                              void* d_out, int out_size) {
    (void)in_sizes; (void)n_in; (void)out_size;
    const float* x  = (const float*)d_in[0];
    const float* a  = (const float*)d_in[1];
    const float* W1 = (const float*)d_in[2];
    const float* W2 = (const float*)d_in[3];
    const float* W3 = (const float*)d_in[4];
    const float* W4 = (const float*)d_in[5];
    const float* s1 = (const float*)d_in[6];
    const float* s2 = (const float*)d_in[7];
    float* out = (float*)d_out;

    k_reset<<<1, 1>>>();
    k_build_csr<<<NN, 256>>>(a);
    k_g1<<<NN / 8, 256>>>(x, W1);
    k_spmm_main<<<NN / 8, 256>>>(s1);
    k_topk<<<1, 1024>>>(0);
    k_subdeg<<<KP1 / 8, 256>>>();
    k_g2<<<KP1 / 8, 256>>>(W2);
    k_spmm_sub<<<KP1 / 8, 256>>>(0, s2);
    k_topk<<<1, 1024>>>(1);
    k_g3<<<KP1 / 8, 256>>>(W3);
    k_spmm_sub<<<KP1 / 8, 256>>>(1, nullptr);
    k_g4<<<NN / 256, 256>>>(W4);
    k_final<<<NN / 8, 256>>>(out);
}

// round 2
// speedup vs baseline: 1.1788x; 1.1788x over previous
#include <cuda_runtime.h>

#define NN     8192
#define KP1    4096
#define KP2    2048
#define FF     32
#define FIN    16
#define MAXDEG 256
#define SUBMAX 192
#define FULLMASK 0xffffffffu

// ---------------- device scratch (static globals; no allocations) -------------
__device__ int    g_rowcnt[NN];
__device__ int    g_cols[NN * MAXDEG];       // padded CSR, rowstart = row*MAXDEG
__device__ int    g_subcnt[KP1];
__device__ int    g_subcols[KP1 * SUBMAX];   // rank-remapped sub CSR
__device__ float  g_dinv[NN];
__device__ float  g_dinvs[KP1];
__device__ float  g_G1[NN * FF];
__device__ float  g_X1[NN * FF];
__device__ float  g_G2[KP1 * FF];
__device__ float  g_X2[KP1 * FF];
__device__ float  g_G3[KP1 * FF];
__device__ float  g_X3[KP1 * FF];
__device__ float2 g_G4[NN];
__device__ float  g_score1[NN];
__device__ float  g_score2[KP1];
__device__ int    g_rank1[NN];
__device__ int    g_rank2[KP1];
__device__ int    g_idx1[KP1];
__device__ int    g_idx2[KP2];

// ---------------- CSR build + dinv + G1 (fused) --------------------------------
// One streaming pass over dense A per block(row): count nnz, warp-scan compact
// into padded CSR, compute dinv, then warp 0 computes G1[row,:] = dinv*(x@W1).
__global__ void k_csr_g1(const float* __restrict__ A,
                         const float* __restrict__ x,
                         const float* __restrict__ W1) {
    int row = blockIdx.x;
    int t   = threadIdx.x;
    int lane = t & 31, wid = t >> 5;

    __shared__ float w1s[FIN * FF];
    __shared__ int   wtot[8];
    __shared__ int   wbase[8];
    __shared__ int   stot;

    if (t < FIN * FF / 2) {            // 512 floats, 2 per thread
        w1s[t]       = W1[t];
        w1s[t + 256] = W1[t + 256];
    }

    const float4* ar = reinterpret_cast<const float4*>(A + (size_t)row * NN);
    float4 v[8];
    int c = 0;
#pragma unroll
    for (int k = 0; k < 8; k++) {
        v[k] = __ldcs(ar + k * 256 + t);
        c += (v[k].x != 0.f) + (v[k].y != 0.f) + (v[k].z != 0.f) + (v[k].w != 0.f);
    }

    // warp inclusive scan of c
    int inc = c;
#pragma unroll
    for (int o = 1; o < 32; o <<= 1) {
        int y = __shfl_up_sync(FULLMASK, inc, o);
        if (lane >= o) inc += y;
    }
    if (lane == 31) wtot[wid] = inc;
    __syncthreads();
    if (t == 0) {
        int s = 0;
#pragma unroll
        for (int i = 0; i < 8; i++) { wbase[i] = s; s += wtot[i]; }
        stot = s;
        g_rowcnt[row] = (s < MAXDEG) ? s : MAXDEG;
        g_dinv[row]   = rsqrtf((float)s + 1.0f + 1e-10f);
    }
    __syncthreads();

    int off = wbase[wid] + inc - c;          // local exclusive offset within row
    int* cp = g_cols + row * MAXDEG;
#pragma unroll
    for (int k = 0; k < 8; k++) {
        int col0 = (k * 256 + t) * 4;
        if (v[k].x != 0.f) { if (off < MAXDEG) cp[off] = col0 + 0; off++; }
        if (v[k].y != 0.f) { if (off < MAXDEG) cp[off] = col0 + 1; off++; }
        if (v[k].z != 0.f) { if (off < MAXDEG) cp[off] = col0 + 2; off++; }
        if (v[k].w != 0.f) { if (off < MAXDEG) cp[off] = col0 + 3; off++; }
    }

    // G1 row by warp 0
    if (wid == 0) {
        float d  = rsqrtf((float)stot + 1.0f + 1e-10f);
        float xv = (lane < FIN) ? x[row * FIN + lane] : 0.f;
        float acc = 0.f;
#pragma unroll
        for (int f = 0; f < FIN; f++) {
            float xf = __shfl_sync(FULLMASK, xv, f);
            acc += xf * w1s[f * FF + lane];
        }
        g_G1[row * FF + lane] = d * acc;
    }
}

// ---------------- main SpMM (vectorized): X1 = relu(dinv*(A_hat @ G1)); score1 -
__global__ void k_spmm_main(const float* __restrict__ s1) {
    __shared__ float sv[FF];
    if (threadIdx.x < FF) sv[threadIdx.x] = s1[threadIdx.x];
    __syncthreads();
    int warp = (blockIdx.x * blockDim.x + threadIdx.x) >> 5;
    int lane = threadIdx.x & 31;
    if (warp >= NN) return;
    int g = lane >> 3, fo = lane & 7;        // g: nnz subgroup, fo: float4 group
    int cnt = g_rowcnt[warp];
    const int* cp = g_cols + warp * MAXDEG;
    const float4* G1v = reinterpret_cast<const float4*>(g_G1);

    float4 acc = make_float4(0.f, 0.f, 0.f, 0.f);
    if (g == 0) acc = G1v[warp * 8 + fo];    // identity (+I) term, once

    for (int k0 = 0; k0 < cnt; k0 += 32) {
        int kc = k0 + lane;
        int mycol = (kc < cnt) ? cp[kc] : -1;
#pragma unroll
        for (int s = 0; s < 8; s++) {
            int c = __shfl_sync(FULLMASK, mycol, s * 4 + g);
            if (c >= 0) {
                float4 tv = G1v[c * 8 + fo];
                acc.x += tv.x; acc.y += tv.y; acc.z += tv.z; acc.w += tv.w;
            }
        }
    }
    // reduce across the 4 nnz subgroups (lanes l, l^8, l^16)
#pragma unroll
    for (int o = 8; o <= 16; o <<= 1) {
        acc.x += __shfl_xor_sync(FULLMASK, acc.x, o);
        acc.y += __shfl_xor_sync(FULLMASK, acc.y, o);
        acc.z += __shfl_xor_sync(FULLMASK, acc.z, o);
        acc.w += __shfl_xor_sync(FULLMASK, acc.w, o);
    }
    float d = g_dinv[warp];
    acc.x = fmaxf(d * acc.x, 0.f); acc.y = fmaxf(d * acc.y, 0.f);
    acc.z = fmaxf(d * acc.z, 0.f); acc.w = fmaxf(d * acc.w, 0.f);
    if (g == 0) reinterpret_cast<float4*>(g_X1)[warp * 8 + fo] = acc;

    // score = X1[warp,:] . s1  (values replicated across groups; reduce 8 lanes)
    float s = acc.x * sv[fo * 4 + 0] + acc.y * sv[fo * 4 + 1] +
              acc.z * sv[fo * 4 + 2] + acc.w * sv[fo * 4 + 3];
    s += __shfl_down_sync(FULLMASK, s, 4);
    s += __shfl_down_sync(FULLMASK, s, 2);
    s += __shfl_down_sync(FULLMASK, s, 1);
    if (lane == 0) g_score1[warp] = s;
}

// ---------------- exact top-K set (radix select + ordered compaction) ----------
__global__ void k_topk(int which) {
    const float* scores = which ? g_score2 : g_score1;
    int  n        = which ? KP1 : NN;
    int  K        = which ? KP2 : KP1;
    int* idx_out  = which ? g_idx2 : g_idx1;
    int* rank_out = which ? g_rank2 : g_rank1;

    __shared__ unsigned su[NN];
    __shared__ int hist[256];
    __shared__ int wagg[32];
    __shared__ int sh_prefix, sh_need;

    int t = threadIdx.x;
    int lane = t & 31, wid = t >> 5;
    int seg = n >> 10;                       // 8 or 4 contiguous elems per thread

    for (int i = t; i < n; i += 1024) {
        unsigned b = __float_as_uint(scores[i]);
        su[i] = (b & 0x80000000u) ? ~b : (b | 0x80000000u);
    }
    if (t == 0) { sh_prefix = 0; sh_need = K; }
    __syncthreads();

    for (int shift = 24; shift >= 0; shift -= 8) {
        if (t < 256) hist[t] = 0;
        __syncthreads();
        unsigned pfx = (unsigned)sh_prefix;
        for (int j = 0; j < seg; j++) {
            unsigned u = su[t * seg + j];
            bool match = (shift == 24) ||
                         ((u >> (shift + 8)) == (pfx >> (shift + 8)));
            if (match) atomicAdd(&hist[(u >> shift) & 255], 1);
        }
        __syncthreads();
        if (t == 0) {
            int need = sh_need;
            int b = 255;
            while (b > 0 && hist[b] < need) { need -= hist[b]; b--; }
            sh_prefix = (int)(pfx | ((unsigned)b << shift));
            sh_need = need;
        }
        __syncthreads();
    }
    unsigned T = (unsigned)sh_prefix;        // exact K-th largest key
    int need_eq = sh_need;                   // #(==T) to take, lowest indices

    // per-thread counts over contiguous segment, one packed block scan
    int gt = 0, eq = 0;
    for (int j = 0; j < seg; j++) {
        unsigned u = su[t * seg + j];
        gt += (u > T); eq += (u == T);
    }
    int packed = (gt << 16) | eq;
    int s = packed;
#pragma unroll
    for (int o = 1; o < 32; o <<= 1) {
        int y = __shfl_up_sync(FULLMASK, s, o);
        if (lane >= o) s += y;
    }
    if (lane == 31) wagg[wid] = s;
    __syncthreads();
    if (wid == 0) {
        int w = wagg[lane];
#pragma unroll
        for (int o = 1; o < 32; o <<= 1) {
            int y = __shfl_up_sync(FULLMASK, w, o);
            if (lane >= o) w += y;
        }
        wagg[lane] = w;
    }
    __syncthreads();
    int excl = s - packed + (wid ? wagg[wid - 1] : 0);
    int gtb = excl >> 16, eqb = excl & 0xffff;

    for (int j = 0; j < seg; j++) {
        int i = t * seg + j;
        unsigned u = su[i];
        bool isgt = (u > T), iseq = (u == T);
        bool sel  = isgt || (iseq && eqb < need_eq);
        int taken_eq = (eqb < need_eq) ? eqb : need_eq;
        int pos = gtb + taken_eq;
        if (sel) { rank_out[i] = pos; idx_out[pos] = i; }
        else       rank_out[i] = -1;
        gtb += isgt; eqb += iseq;
    }
}

// ---------------- sub-CSR build + dinvs + G2 (fused) ---------------------------
__global__ void k_sub(const float* __restrict__ W2) {
    __shared__ float w[FF * FF];
    for (int i = threadIdx.x; i < FF * FF; i += blockDim.x) w[i] = W2[i];
    __syncthreads();
    int r = (blockIdx.x * blockDim.x + threadIdx.x) >> 5;
    int lane = threadIdx.x & 31;
    if (r >= KP1) return;
    int i = g_idx1[r];
    int cnt = g_rowcnt[i];
    const int* cp = g_cols + i * MAXDEG;
    int* sp = g_subcols + r * SUBMAX;
    unsigned lt = (1u << lane) - 1u;
    int wcnt = 0;
    for (int k0 = 0; k0 < cnt; k0 += 32) {
        int k = k0 + lane;
        int rr = -1; int ok = 0;
        if (k < cnt) { rr = g_rank1[cp[k]]; ok = (rr >= 0); }
        unsigned m = __ballot_sync(FULLMASK, ok);
        if (ok) { int p = wcnt + __popc(m & lt); if (p < SUBMAX) sp[p] = rr; }
        wcnt += __popc(m);
    }
    float di = rsqrtf((float)wcnt + 1.0f + 1e-10f);
    if (lane == 0) {
        g_subcnt[r] = (wcnt < SUBMAX) ? wcnt : SUBMAX;
        g_dinvs[r]  = di;
    }
    // G2 row
    float xv = g_X1[i * FF + lane];
    float acc = 0.f;
#pragma unroll
    for (int f = 0; f < FF; f++) {
        float xf = __shfl_sync(FULLMASK, xv, f);
        acc += xf * w[f * FF + lane];
    }
    g_G2[r * FF + lane] = di * acc;
}

// ---------------- subgraph SpMM (vectorized, pre-filtered sub-CSR) -------------
// phase 0: G2 -> X2 (+score2 via s2).  phase 1: G3 -> X3.
__global__ void k_spmm_sub(int phase, const float* __restrict__ svec) {
    __shared__ float sv[FF];
    if (phase == 0 && threadIdx.x < FF) sv[threadIdx.x] = svec[threadIdx.x];
    __syncthreads();
    const float4* Gv = reinterpret_cast<const float4*>(phase ? g_G3 : g_G2);
    float4*       Xv = reinterpret_cast<float4*>(phase ? g_X3 : g_X2);
    int r = (blockIdx.x * blockDim.x + threadIdx.x) >> 5;
    int lane = threadIdx.x & 31;
    if (r >= KP1) return;
    int g = lane >> 3, fo = lane & 7;
    int cnt = g_subcnt[r];
    const int* sp = g_subcols + r * SUBMAX;

    float4 acc = make_float4(0.f, 0.f, 0.f, 0.f);
    if (g == 0) acc = Gv[r * 8 + fo];
    for (int k0 = 0; k0 < cnt; k0 += 32) {
        int kc = k0 + lane;
        int mycol = (kc < cnt) ? sp[kc] : -1;
#pragma unroll
        for (int s = 0; s < 8; s++) {
            int c = __shfl_sync(FULLMASK, mycol, s * 4 + g);
            if (c >= 0) {
                float4 tv = Gv[c * 8 + fo];
                acc.x += tv.x; acc.y += tv.y; acc.z += tv.z; acc.w += tv.w;
            }
        }
    }
#pragma unroll
    for (int o = 8; o <= 16; o <<= 1) {
        acc.x += __shfl_xor_sync(FULLMASK, acc.x, o);
        acc.y += __shfl_xor_sync(FULLMASK, acc.y, o);
        acc.z += __shfl_xor_sync(FULLMASK, acc.z, o);
        acc.w += __shfl_xor_sync(FULLMASK, acc.w, o);
    }
    float d = g_dinvs[r];
    acc.x = fmaxf(d * acc.x, 0.f); acc.y = fmaxf(d * acc.y, 0.f);
    acc.z = fmaxf(d * acc.z, 0.f); acc.w = fmaxf(d * acc.w, 0.f);
    if (g == 0) Xv[r * 8 + fo] = acc;
    if (phase == 0) {
        float s = acc.x * sv[fo * 4 + 0] + acc.y * sv[fo * 4 + 1] +
                  acc.z * sv[fo * 4 + 2] + acc.w * sv[fo * 4 + 3];
        s += __shfl_down_sync(FULLMASK, s, 4);
        s += __shfl_down_sync(FULLMASK, s, 2);
        s += __shfl_down_sync(FULLMASK, s, 1);
        if (lane == 0) g_score2[r] = s;
    }
}

// ---------------- G3 = (rank2>=0) ? dinvs*(X2@W3) : 0  (unpool-2 fused) --------
__global__ void k_g3(const float* __restrict__ W3) {
    __shared__ float w[FF * FF];
    for (int i = threadIdx.x; i < FF * FF; i += blockDim.x) w[i] = W3[i];
    __syncthreads();
    int r = (blockIdx.x * blockDim.x + threadIdx.x) >> 5;
    int lane = threadIdx.x & 31;
    if (r >= KP1) return;
    if (g_rank2[r] < 0) { g_G3[r * FF + lane] = 0.f; return; }
    float xv = g_X2[r * FF + lane];
    float acc = 0.f;
#pragma unroll
    for (int f = 0; f < FF; f++) {
        float xf = __shfl_sync(FULLMASK, xv, f);
        acc += xf * w[f * FF + lane];
    }
    g_G3[r * FF + lane] = g_dinvs[r] * acc;
}

// ---------------- G4 = dinv * (unpool1(X3) @ W4) -------------------------------
__global__ void k_g4(const float* __restrict__ W4) {
    __shared__ float w[FF * 2];
    for (int i = threadIdx.x; i < FF * 2; i += blockDim.x) w[i] = W4[i];
    __syncthreads();
    int i = blockIdx.x * blockDim.x + threadIdx.x;
    if (i >= NN) return;
    int rr = g_rank1[i];
    float h0 = 0.f, h1 = 0.f;
    if (rr >= 0) {
        const float4* xr = reinterpret_cast<const float4*>(g_X3 + rr * FF);
#pragma unroll
        for (int q = 0; q < 8; q++) {
            float4 xv = xr[q];
            h0 += xv.x * w[(q * 4 + 0) * 2] + xv.y * w[(q * 4 + 1) * 2] +
                  xv.z * w[(q * 4 + 2) * 2] + xv.w * w[(q * 4 + 3) * 2];
            h1 += xv.x * w[(q * 4 + 0) * 2 + 1] + xv.y * w[(q * 4 + 1) * 2 + 1] +
                  xv.z * w[(q * 4 + 2) * 2 + 1] + xv.w * w[(q * 4 + 3) * 2 + 1];
        }
    }
    float d = g_dinv[i];
    g_G4[i] = make_float2(d * h0, d * h1);
}

// ---------------- final SpMM (F=2) + normalization + softmax -------------------
__global__ void k_final(float* __restrict__ out) {
    int warp = (blockIdx.x * blockDim.x + threadIdx.x) >> 5;
    int lane = threadIdx.x & 31;
    if (warp >= NN) return;
    int cnt = g_rowcnt[warp];
    const int* cp = g_cols + warp * MAXDEG;
    float a0 = 0.f, a1 = 0.f;
    for (int k = lane; k < cnt; k += 32) {
        float2 gv = g_G4[cp[k]];
        a0 += gv.x; a1 += gv.y;
    }
#pragma unroll
    for (int o = 16; o > 0; o >>= 1) {
        a0 += __shfl_down_sync(FULLMASK, a0, o);
        a1 += __shfl_down_sync(FULLMASK, a1, o);
    }
    if (lane == 0) {
        float2 gs = g_G4[warp];
        float d = g_dinv[warp];
        float y0 = d * (a0 + gs.x);
        float y1 = d * (a1 + gs.y);
        float m = fmaxf(y0, y1);
        float e0 = expf(y0 - m);
        float e1 = expf(y1 - m);
        float inv = 1.0f / (e0 + e1);
        out[warp * 2 + 0] = e0 * inv;
        out[warp * 2 + 1] = e1 * inv;
    }
}

// ---------------- launcher ----------------------------------------------------
extern "C" void kernel_launch(void* const* d_in, const int* in_sizes, int n_in,
                              void* d_out, int out_size) {
    (void)in_sizes; (void)n_in; (void)out_size;
    const float* x  = (const float*)d_in[0];
    const float* a  = (const float*)d_in[1];
    const float* W1 = (const float*)d_in[2];
    const float* W2 = (const float*)d_in[3];
    const float* W3 = (const float*)d_in[4];
    const float* W4 = (const float*)d_in[5];
    const float* s1 = (const float*)d_in[6];
    const float* s2 = (const float*)d_in[7];
    float* out = (float*)d_out;

    k_csr_g1<<<NN, 256>>>(a, x, W1);
    k_spmm_main<<<NN / 8, 256>>>(s1);
    k_topk<<<1, 1024>>>(0);
    k_sub<<<KP1 / 8, 256>>>(W2);
    k_spmm_sub<<<KP1 / 8, 256>>>(0, s2);
    k_topk<<<1, 1024>>>(1);
    k_g3<<<KP1 / 8, 256>>>(W3);
    k_spmm_sub<<<KP1 / 8, 256>>>(1, nullptr);
    k_g4<<<NN / 256, 256>>>(W4);
    k_final<<<NN / 8, 256>>>(out);
}